// round 7
// baseline (speedup 1.0000x reference)
#include <cuda_runtime.h>
#include <cuda_bf16.h>

// db4 level-1 DWT low-pass reconstruction. Persistent grid-stride CTAs with
// cross-row software pipelining (prefetch next row while computing current),
// shuffle halos, no shared memory, streaming stores.
// x: [8192 rows, 4096] fp32. out = low (N floats) then high (N floats).
//
//   ca[K]     = sum_{m=0..7} h[m] * X(2K+1-m)     (X = symmetric-ext x)
//   low[2K]   = h1*ca[K] + h3*ca[K+1] + h5*ca[K+2] + h7*ca[K+3]
//   low[2K+1] = h0*ca[K] + h2*ca[K+1] + h4*ca[K+2] + h6*ca[K+3]
//   high      = x - low

#define ROW_L    4096
#define NTHREADS 256
#define NF4      (ROW_L / 4)     // 1024 float4 per row
#define GRID_CTAS 608            // ~4 CTAs per SM target

__global__ void __launch_bounds__(NTHREADS)
dwt_db4_kernel(const float* __restrict__ x,
               float* __restrict__ low_out,
               float* __restrict__ high_out,
               int nrows)
{
    const float h0 = -0.010597401784997278f;
    const float h1 =  0.032883011666982945f;
    const float h2 =  0.030841381835986965f;
    const float h3 = -0.18703481171888114f;
    const float h4 = -0.02798376941698385f;
    const float h5 =  0.6308807679295904f;
    const float h6 =  0.7148465705525415f;
    const float h7 =  0.23037781330885523f;

    const int t = threadIdx.x;
    const int l = t & 31;
    const int stride = gridDim.x;

    int row = blockIdx.x;
    if (row >= nrows) return;

    // Prologue: load current row (MLP = 4)
    float4 vv[4];
    {
        const float4* __restrict__ p = (const float4*)(x + (size_t)row * ROW_L);
        #pragma unroll
        for (int g = 0; g < 4; ++g)
            vv[g] = p[g * NTHREADS + t];
    }

    while (true) {
        const int next = row + stride;

        // Prefetch next row early — overlaps with compute below
        float4 nv[4];
        if (next < nrows) {
            const float4* __restrict__ p = (const float4*)(x + (size_t)next * ROW_L);
            #pragma unroll
            for (int g = 0; g < 4; ++g)
                nv[g] = p[g * NTHREADS + t];
        }

        const float4* __restrict__ xr4 = (const float4*)(x + (size_t)row * ROW_L);
        float* __restrict__ lowp  = low_out  + (size_t)row * ROW_L;
        float* __restrict__ highp = high_out + (size_t)row * ROW_L;

        #pragma unroll
        for (int g = 0; g < 4; ++g) {
            const int F = g * NTHREADS + t;          // float4 index in row
            const float4 v = vv[g];

            // window w[i] = X(4F - 6 + i), i = 0..15
            float w0, w1, w2, w3, w4, w5;
            float w6 = v.x, w7 = v.y, w8 = v.z, w9 = v.w;
            float w10, w11, w12, w13, w14, w15;

            // halos via shuffle (full-warp convergent)
            w2  = __shfl_up_sync(0xffffffffu, v.x, 1);
            w3  = __shfl_up_sync(0xffffffffu, v.y, 1);
            w4  = __shfl_up_sync(0xffffffffu, v.z, 1);
            w5  = __shfl_up_sync(0xffffffffu, v.w, 1);
            w0  = __shfl_up_sync(0xffffffffu, v.z, 2);
            w1  = __shfl_up_sync(0xffffffffu, v.w, 2);
            w10 = __shfl_down_sync(0xffffffffu, v.x, 1);
            w11 = __shfl_down_sync(0xffffffffu, v.y, 1);
            w12 = __shfl_down_sync(0xffffffffu, v.z, 1);
            w13 = __shfl_down_sync(0xffffffffu, v.w, 1);
            w14 = __shfl_down_sync(0xffffffffu, v.x, 2);
            w15 = __shfl_down_sync(0xffffffffu, v.y, 2);

            // warp-edge patches: vectorized predicated loads (L1/L2-hot),
            // explicit swizzle for the rare row-end reflected cases.
            if (l == 0) {
                // need x[4F-6 .. 4F-1]
                const bool refl = (F == 0);
                const float4 A = xr4[refl ? 1 : F - 2];
                const float4 B = xr4[refl ? 0 : F - 1];
                if (refl) { w0 = A.y; w1 = A.x; w2 = B.w; w3 = B.z; w4 = B.y; w5 = B.x; }
                else      { w0 = A.z; w1 = A.w; w2 = B.x; w3 = B.y; w4 = B.z; w5 = B.w; }
            } else if (l == 1) {
                // need x[4F-6], x[4F-5]
                const bool refl = (F == 1);
                const float4 A = xr4[refl ? 0 : F - 2];
                if (refl) { w0 = A.y; w1 = A.x; }
                else      { w0 = A.z; w1 = A.w; }
            }
            if (l == 31) {
                // need x[4F+4 .. 4F+9]
                const bool refl = (F == NF4 - 1);
                const float4 C = xr4[refl ? (NF4 - 1) : F + 1];
                const float4 D = xr4[refl ? (NF4 - 2) : F + 2];
                if (refl) { w10 = C.w; w11 = C.z; w12 = C.y; w13 = C.x; w14 = D.w; w15 = D.z; }
                else      { w10 = C.x; w11 = C.y; w12 = C.z; w13 = C.w; w14 = D.x; w15 = D.y; }
            } else if (l == 30) {
                // need x[4F+8], x[4F+9]
                const bool refl = (F == NF4 - 2);
                const float4 D = xr4[refl ? (NF4 - 1) : F + 2];
                if (refl) { w14 = D.w; w15 = D.z; }
                else      { w14 = D.x; w15 = D.y; }
            }

            // analysis: ca[j] (global coeff index 2F + j), j = 0..4
            // ca_j = sum_m h[m] * w[2j + 7 - m]
            float wv[16] = { w0, w1, w2, w3, w4, w5, w6, w7,
                             w8, w9, w10, w11, w12, w13, w14, w15 };
            float ca[5];
            #pragma unroll
            for (int j = 0; j < 5; ++j) {
                float s;
                s = h0 * wv[2 * j + 7];
                s = fmaf(h1, wv[2 * j + 6], s);
                s = fmaf(h2, wv[2 * j + 5], s);
                s = fmaf(h3, wv[2 * j + 4], s);
                s = fmaf(h4, wv[2 * j + 3], s);
                s = fmaf(h5, wv[2 * j + 2], s);
                s = fmaf(h6, wv[2 * j + 1], s);
                s = fmaf(h7, wv[2 * j + 0], s);
                ca[j] = s;
            }

            // synthesis: pairs p = 0,1 -> outputs x[4F .. 4F+3]
            float le[2], lo[2];
            #pragma unroll
            for (int p = 0; p < 2; ++p) {
                float e;
                e = h1 * ca[p];
                e = fmaf(h3, ca[p + 1], e);
                e = fmaf(h5, ca[p + 2], e);
                e = fmaf(h7, ca[p + 3], e);
                le[p] = e;

                float o;
                o = h0 * ca[p];
                o = fmaf(h2, ca[p + 1], o);
                o = fmaf(h4, ca[p + 2], o);
                o = fmaf(h6, ca[p + 3], o);
                lo[p] = o;
            }

            // streaming stores (outputs never re-read; keep them out of L2)
            __stcs((float4*)(lowp)  + F, make_float4(le[0], lo[0], le[1], lo[1]));
            __stcs((float4*)(highp) + F, make_float4(w6 - le[0], w7 - lo[0],
                                                     w8 - le[1], w9 - lo[1]));
        }

        if (next >= nrows) break;
        row = next;
        #pragma unroll
        for (int g = 0; g < 4; ++g)
            vv[g] = nv[g];
    }
}

extern "C" void kernel_launch(void* const* d_in, const int* in_sizes, int n_in,
                              void* d_out, int out_size)
{
    const float* x = (const float*)d_in[0];
    const int n = in_sizes[0];            // 16*512*4096
    float* low  = (float*)d_out;          // outputs concatenated: (low, high)
    float* high = low + (size_t)n;
    const int rows = n / ROW_L;           // 8192
    dwt_db4_kernel<<<GRID_CTAS, NTHREADS>>>(x, low, high, rows);
}

// round 8
// speedup vs baseline: 1.2342x; 1.2342x over previous
#include <cuda_runtime.h>
#include <cuda_bf16.h>

// db4 level-1 DWT low-pass reconstruction. Shuffle halos, no shared memory,
// front-batched loads (MLP=4), vectorized edge patches, streaming stores.
// x: [8192 rows, 4096] fp32. out = low (N floats) then high (N floats).
//
//   ca[K]     = sum_{m=0..7} h[m] * X(2K+1-m)     (X = symmetric-ext x)
//   low[2K]   = h1*ca[K] + h3*ca[K+1] + h5*ca[K+2] + h7*ca[K+3]
//   low[2K+1] = h0*ca[K] + h2*ca[K+1] + h4*ca[K+2] + h6*ca[K+3]
//   high      = x - low

#define ROW_L    4096
#define NTHREADS 256
#define NF4      (ROW_L / 4)     // 1024 float4 per row

__global__ void __launch_bounds__(NTHREADS)
dwt_db4_kernel(const float* __restrict__ x,
               float* __restrict__ low_out,
               float* __restrict__ high_out)
{
    const float h0 = -0.010597401784997278f;
    const float h1 =  0.032883011666982945f;
    const float h2 =  0.030841381835986965f;
    const float h3 = -0.18703481171888114f;
    const float h4 = -0.02798376941698385f;
    const float h5 =  0.6308807679295904f;
    const float h6 =  0.7148465705525415f;
    const float h7 =  0.23037781330885523f;

    const int t = threadIdx.x;
    const int l = t & 31;
    const size_t row = blockIdx.x;
    const float4* __restrict__ xr4 = (const float4*)(x + row * (size_t)ROW_L);
    float4* __restrict__ low4  = (float4*)(low_out  + row * (size_t)ROW_L);
    float4* __restrict__ high4 = (float4*)(high_out + row * (size_t)ROW_L);

    // Front-batched main loads: MLP = 4
    float4 vv[4];
    #pragma unroll
    for (int g = 0; g < 4; ++g)
        vv[g] = xr4[g * NTHREADS + t];

    #pragma unroll
    for (int g = 0; g < 4; ++g) {
        const int F = g * NTHREADS + t;          // float4 index in row
        const float4 v = vv[g];

        // window w[i] = X(4F - 6 + i), i = 0..15
        float w0, w1, w2, w3, w4, w5;
        float w6 = v.x, w7 = v.y, w8 = v.z, w9 = v.w;
        float w10, w11, w12, w13, w14, w15;

        // halos via shuffle (full-warp convergent)
        w2  = __shfl_up_sync(0xffffffffu, v.x, 1);
        w3  = __shfl_up_sync(0xffffffffu, v.y, 1);
        w4  = __shfl_up_sync(0xffffffffu, v.z, 1);
        w5  = __shfl_up_sync(0xffffffffu, v.w, 1);
        w0  = __shfl_up_sync(0xffffffffu, v.z, 2);
        w1  = __shfl_up_sync(0xffffffffu, v.w, 2);
        w10 = __shfl_down_sync(0xffffffffu, v.x, 1);
        w11 = __shfl_down_sync(0xffffffffu, v.y, 1);
        w12 = __shfl_down_sync(0xffffffffu, v.z, 1);
        w13 = __shfl_down_sync(0xffffffffu, v.w, 1);
        w14 = __shfl_down_sync(0xffffffffu, v.x, 2);
        w15 = __shfl_down_sync(0xffffffffu, v.y, 2);

        // warp-edge patches: vectorized predicated loads (L2-hot), with
        // explicit swizzle for the (rare) row-end reflected cases.
        if (l == 0) {
            // need x[4F-6 .. 4F-1]
            const bool refl = (F == 0);
            const float4 A = xr4[refl ? 1 : F - 2];
            const float4 B = xr4[refl ? 0 : F - 1];
            if (refl) { w0 = A.y; w1 = A.x; w2 = B.w; w3 = B.z; w4 = B.y; w5 = B.x; }
            else      { w0 = A.z; w1 = A.w; w2 = B.x; w3 = B.y; w4 = B.z; w5 = B.w; }
        } else if (l == 1) {
            // need x[4F-6], x[4F-5]
            const bool refl = (F == 1);
            const float4 A = xr4[refl ? 0 : F - 2];
            if (refl) { w0 = A.y; w1 = A.x; }
            else      { w0 = A.z; w1 = A.w; }
        }
        if (l == 31) {
            // need x[4F+4 .. 4F+9]
            const bool refl = (F == NF4 - 1);
            const float4 C = xr4[refl ? (NF4 - 1) : F + 1];
            const float4 D = xr4[refl ? (NF4 - 2) : F + 2];
            if (refl) { w10 = C.w; w11 = C.z; w12 = C.y; w13 = C.x; w14 = D.w; w15 = D.z; }
            else      { w10 = C.x; w11 = C.y; w12 = C.z; w13 = C.w; w14 = D.x; w15 = D.y; }
        } else if (l == 30) {
            // need x[4F+8], x[4F+9]
            const bool refl = (F == NF4 - 2);
            const float4 D = xr4[refl ? (NF4 - 1) : F + 2];
            if (refl) { w14 = D.w; w15 = D.z; }
            else      { w14 = D.x; w15 = D.y; }
        }

        // analysis: ca[j] (global coeff index 2F + j), j = 0..4
        // ca_j = sum_m h[m] * w[2j + 7 - m]
        float wv[16] = { w0, w1, w2, w3, w4, w5, w6, w7,
                         w8, w9, w10, w11, w12, w13, w14, w15 };
        float ca[5];
        #pragma unroll
        for (int j = 0; j < 5; ++j) {
            float s;
            s = h0 * wv[2 * j + 7];
            s = fmaf(h1, wv[2 * j + 6], s);
            s = fmaf(h2, wv[2 * j + 5], s);
            s = fmaf(h3, wv[2 * j + 4], s);
            s = fmaf(h4, wv[2 * j + 3], s);
            s = fmaf(h5, wv[2 * j + 2], s);
            s = fmaf(h6, wv[2 * j + 1], s);
            s = fmaf(h7, wv[2 * j + 0], s);
            ca[j] = s;
        }

        // synthesis: pairs p = 0,1 -> outputs x[4F .. 4F+3]
        float le[2], lo[2];
        #pragma unroll
        for (int p = 0; p < 2; ++p) {
            float e;
            e = h1 * ca[p];
            e = fmaf(h3, ca[p + 1], e);
            e = fmaf(h5, ca[p + 2], e);
            e = fmaf(h7, ca[p + 3], e);
            le[p] = e;

            float o;
            o = h0 * ca[p];
            o = fmaf(h2, ca[p + 1], o);
            o = fmaf(h4, ca[p + 2], o);
            o = fmaf(h6, ca[p + 3], o);
            lo[p] = o;
        }

        // streaming stores: outputs are write-once, keep them out of L2's
        // working set so input lines (edge-patch reuse) stay resident.
        __stcs(low4  + F, make_float4(le[0], lo[0], le[1], lo[1]));
        __stcs(high4 + F, make_float4(w6 - le[0], w7 - lo[0],
                                      w8 - le[1], w9 - lo[1]));
    }
}

extern "C" void kernel_launch(void* const* d_in, const int* in_sizes, int n_in,
                              void* d_out, int out_size)
{
    const float* x = (const float*)d_in[0];
    const int n = in_sizes[0];            // 16*512*4096
    float* low  = (float*)d_out;          // outputs concatenated: (low, high)
    float* high = low + (size_t)n;
    const int rows = n / ROW_L;           // 8192
    dwt_db4_kernel<<<rows, NTHREADS>>>(x, low, high);
}